// round 2
// baseline (speedup 1.0000x reference)
#include <cuda_runtime.h>

#define NN 30000
#define EE 480000

// ---- device scratch (no allocs allowed) ----
__device__ float4 g_aggA[NN * 32];   // per node, 32 ch x {s_a, v_a.xyz}
__device__ float4 g_aggB[NN * 32];   // per node, 32 ch x {s_b, v_b.xyz}
__device__ float  g_x0[NN * 32];
__device__ float  g_x1[NN * 96];
__device__ int    g_count[NN];
__device__ int    g_offset[NN + 1];
__device__ int    g_cursor[NN];
__device__ int    g_sorted[EE];

// ---------------------------------------------------------------------------
// x0 = node_s @ W1_0 * inv_m ; x1[n,w,d] = sum_u node_v[n,u,d]*W1_1[u,w]*inv_m
// Also zeroes g_count (one per node).
__global__ void node_pre_kernel(const float* __restrict__ node_s,
                                const float* __restrict__ node_v,
                                const float* __restrict__ W1_0,
                                const float* __restrict__ W1_1) {
    __shared__ float w0s[1024], w1s[1024];
    for (int i = threadIdx.x; i < 1024; i += blockDim.x) {
        w0s[i] = W1_0[i];
        w1s[i] = W1_1[i];
    }
    __syncthreads();
    int warp = (blockIdx.x * blockDim.x + threadIdx.x) >> 5;
    int lane = threadIdx.x & 31;
    if (warp >= NN) return;
    if (lane == 0) g_count[warp] = 0;

    float s  = node_s[warp * 32 + lane];
    float v0 = node_v[warp * 96 + lane * 3 + 0];
    float v1 = node_v[warp * 96 + lane * 3 + 1];
    float v2 = node_v[warp * 96 + lane * 3 + 2];

    float x0 = 0.f, a0 = 0.f, a1 = 0.f, a2 = 0.f;
#pragma unroll
    for (int u = 0; u < 32; u++) {
        float su  = __shfl_sync(0xffffffffu, s,  u);
        float vu0 = __shfl_sync(0xffffffffu, v0, u);
        float vu1 = __shfl_sync(0xffffffffu, v1, u);
        float vu2 = __shfl_sync(0xffffffffu, v2, u);
        float w0 = w0s[u * 32 + lane];
        float w1 = w1s[u * 32 + lane];
        x0 = fmaf(su, w0, x0);
        a0 = fmaf(vu0, w1, a0);
        a1 = fmaf(vu1, w1, a1);
        a2 = fmaf(vu2, w1, a2);
    }
    const float inv_m = 0.17677669529663687f;  // 1/sqrt(32)
    g_x0[warp * 32 + lane]         = x0 * inv_m;
    g_x1[warp * 96 + lane * 3 + 0] = a0 * inv_m;
    g_x1[warp * 96 + lane * 3 + 1] = a1 * inv_m;
    g_x1[warp * 96 + lane * 3 + 2] = a2 * inv_m;
}

// ---------------------------------------------------------------------------
__global__ void hist_kernel(const int* __restrict__ edge_src) {
    int i = blockIdx.x * blockDim.x + threadIdx.x;
    if (i < EE) atomicAdd(&g_count[edge_src[i]], 1);
}

// Single-block exclusive scan of g_count -> g_offset / g_cursor.
__global__ void scan_kernel() {
    __shared__ int ps[1024];
    int tid = threadIdx.x;
    const int CH = 30;  // 1024*30 >= NN
    int base = tid * CH;
    int s = 0;
    for (int i = 0; i < CH; i++) {
        int idx = base + i;
        if (idx < NN) s += g_count[idx];
    }
    ps[tid] = s;
    __syncthreads();
    for (int off = 1; off < 1024; off <<= 1) {
        int t = (tid >= off) ? ps[tid - off] : 0;
        __syncthreads();
        ps[tid] += t;
        __syncthreads();
    }
    int run = ps[tid] - s;  // exclusive prefix
    for (int i = 0; i < CH; i++) {
        int idx = base + i;
        if (idx < NN) {
            g_offset[idx] = run;
            g_cursor[idx] = run;
            run += g_count[idx];
        }
    }
    if (tid == 0) g_offset[NN] = EE;
}

__global__ void scatter_kernel(const int* __restrict__ edge_src) {
    int i = blockIdx.x * blockDim.x + threadIdx.x;
    if (i < EE) {
        int s = edge_src[i];
        int p = atomicAdd(&g_cursor[s], 1);
        g_sorted[p] = i;
    }
}

// ---------------------------------------------------------------------------
// Warp per src node: walk CSR edge list, accumulate in registers, one store.
__global__ void edge_agg_kernel(const float* __restrict__ edge_attr,
                                const float* __restrict__ edge_scalars,
                                const float* __restrict__ Wfc1,
                                const float* __restrict__ Wfc2,
                                const int*   __restrict__ edge_dst) {
    __shared__ float fc1s[64], fc2s[1024];
    for (int i = threadIdx.x; i < 64; i += blockDim.x) fc1s[i] = Wfc1[i];
    for (int i = threadIdx.x; i < 1024; i += blockDim.x) fc2s[i] = Wfc2[i];
    __syncthreads();

    int n = blockIdx.x * 8 + (threadIdx.x >> 5);
    int lane = threadIdx.x & 31;
    if (n >= NN) return;

    int beg = g_offset[n], end = g_offset[n + 1];

    float aA0 = 0.f, aA1 = 0.f, aA2 = 0.f, aA3 = 0.f;
    float aB0 = 0.f, aB1 = 0.f, aB2 = 0.f, aB3 = 0.f;

    const float inv8 = 0.35355339059327373f;        // 1/sqrt(8)
    const float INV_SQRT3 = 0.5773502691896258f;

    for (int i = beg; i < end; i++) {
        int e = g_sorted[i];

        // --- h = ssp(es @ Wfc1 * inv8): lanes 0..7 compute one output each
        float hv = 0.f;
        if (lane < 8) {
            float acc = 0.f;
#pragma unroll
            for (int k = 0; k < 8; k++)
                acc = fmaf(edge_scalars[e * 8 + k], fc1s[k * 8 + lane], acc);
            acc *= inv8;
            float ex = __expf(-fabsf(acc));
            hv = fmaxf(acc, 0.f) + log1pf(ex) - 0.6931471805599453f;
        }
        float h[8];
#pragma unroll
        for (int j = 0; j < 8; j++) h[j] = __shfl_sync(0xffffffffu, hv, j);

        // --- w = h @ Wfc2 * inv8
        float w00 = 0.f, w01 = 0.f, w10 = 0.f, w11 = 0.f;
#pragma unroll
        for (int j = 0; j < 8; j++) {
            const float* r = &fc2s[j * 128 + lane];
            w00 = fmaf(h[j], r[0],  w00);
            w01 = fmaf(h[j], r[32], w01);
            w10 = fmaf(h[j], r[64], w10);
            w11 = fmaf(h[j], r[96], w11);
        }
        w00 *= inv8; w01 *= inv8; w10 *= inv8; w11 *= inv8;

        int dstn = edge_dst[e];

        float x0 = g_x0[dstn * 32 + lane];
        float y0 = g_x1[dstn * 96 + lane * 3 + 0];
        float y1 = g_x1[dstn * 96 + lane * 3 + 1];
        float y2 = g_x1[dstn * 96 + lane * 3 + 2];

        float sh0 = edge_attr[e * 4 + 0];
        float sh1 = edge_attr[e * 4 + 1];
        float sh2 = edge_attr[e * 4 + 2];
        float sh3 = edge_attr[e * 4 + 3];

        float s_a = w00 * x0 * sh0;
        float dot = fmaf(y0, sh1, fmaf(y1, sh2, y2 * sh3));
        float s_b = w11 * dot * INV_SQRT3;
        float p = w01 * x0;
        float q = w10 * sh0;

        aA0 += s_a;     aA1 += p * sh1; aA2 += p * sh2; aA3 += p * sh3;
        aB0 += s_b;     aB1 += q * y0;  aB2 += q * y1;  aB3 += q * y2;
    }

    g_aggA[n * 32 + lane] = make_float4(aA0, aA1, aA2, aA3);
    g_aggB[n * 32 + lane] = make_float4(aB0, aB1, aB2, aB3);
}

// ---------------------------------------------------------------------------
// node_post v2: 256 thr / 16 nodes per block; weights staged in dynamic smem.
// A-phase shares each Wsc LDS.128 across a pair of nodes; A stored transposed
// (pad 36) and W2 transposed (pad 68) so consume is conflict-free LDS.128.
#define OFF_WSC0 0          // 8192  Wsc0[u*256+v*32+w]
#define OFF_WSC1 8192       // 8192
#define OFF_W20  16384      // 32*68 = 2176   W20t[w*68+k] = W2_0[k*32+w]
#define OFF_W21  18560      // 2176
#define OFF_A0   20736      // 2*1152         A0t[t][w*36+u]
#define OFF_A1   23040      // 2*1152
#define OFF_S    25344      // 2*32
#define OFF_VD   25408      // 2*96           sVd[t][d*32+u]
#define OFF_AT   25600      // 2*8
#define OFF_AGS  25616      // 2*64           agg_s[t][k]
#define OFF_AGV  25744      // 2*192          agg_v[t][d*64+k]
#define SM_FLOATS 26128
#define SM_BYTES (SM_FLOATS * 4)

__global__ void node_post2_kernel(const float* __restrict__ node_s,
                                  const float* __restrict__ node_v,
                                  const float* __restrict__ node_attr,
                                  const float* __restrict__ W2_0,
                                  const float* __restrict__ W2_1,
                                  const float* __restrict__ Wsc0,
                                  const float* __restrict__ Wsc1,
                                  float* __restrict__ out) {
    extern __shared__ float sm[];
    int tid = threadIdx.x;
    int nbase = blockIdx.x * 16;

    // stage weights (once per block)
    for (int i = tid; i < 8192; i += 256) sm[OFF_WSC0 + i] = Wsc0[i];
    for (int i = tid; i < 8192; i += 256) sm[OFF_WSC1 + i] = Wsc1[i];
    for (int i = tid; i < 2048; i += 256) {
        int k = i >> 5, w = i & 31;
        sm[OFF_W20 + w * 68 + k] = W2_0[i];
        sm[OFF_W21 + w * 68 + k] = W2_1[i];
    }

    const float c_agg = 0.03125f;  // 1/sqrt(64)*1/sqrt(16)
    const float c_sc  = 0.0625f;   // 1/sqrt(32*8)

    for (int p = 0; p < 8; p++) {
        int n0 = nbase + 2 * p;
        __syncthreads();  // prev consume done (and weights staged on p==0)

        // --- stage the pair's per-node data ---
        if (tid < 64) {
            int t = tid >> 5, u = tid & 31;
            sm[OFF_S + tid] = node_s[(n0 + t) * 32 + u];
        }
        if (tid < 192) {
            int t = tid / 96, r = tid % 96;
            int d = r >> 5, u = r & 31;
            sm[OFF_VD + t * 96 + d * 32 + u] = node_v[(n0 + t) * 96 + u * 3 + d];
        }
        if (tid < 16) {
            int t = tid >> 3, v = tid & 7;
            sm[OFF_AT + tid] = node_attr[(n0 + t) * 8 + v];
        }
        if (tid < 128) {
            int t = tid >> 6, k = tid & 63;
            float4 q = (k < 32) ? g_aggA[(n0 + t) * 32 + k]
                                : g_aggB[(n0 + t) * 32 + (k - 32)];
            sm[OFF_AGS + t * 64 + k] = q.x;
            sm[OFF_AGV + t * 192 + 0 * 64 + k] = q.y;
            sm[OFF_AGV + t * 192 + 1 * 64 + k] = q.z;
            sm[OFF_AGV + t * 192 + 2 * 64 + k] = q.w;
        }
        __syncthreads();

        // --- A-phase: A0/A1 for both nodes, each weight LDS.128 used twice ---
        float at0[8], at1[8];
#pragma unroll
        for (int v = 0; v < 8; v++) {
            at0[v] = sm[OFF_AT + v];
            at1[v] = sm[OFF_AT + 8 + v];
        }
#pragma unroll
        for (int r4 = 0; r4 < 2; r4++) {
            int g = r4 * 256 + tid;
            int which = g >> 8;
            int gi = g & 255;
            int u = gi >> 3;
            int w4 = (gi & 7) << 2;
            const float4* W4 = (const float4*)&sm[(which ? OFF_WSC1 : OFF_WSC0)
                                                  + u * 256 + w4];
            float4 a0 = make_float4(0.f, 0.f, 0.f, 0.f);
            float4 a1 = make_float4(0.f, 0.f, 0.f, 0.f);
#pragma unroll
            for (int v = 0; v < 8; v++) {
                float4 wv = W4[v * 8];
                a0.x = fmaf(at0[v], wv.x, a0.x); a1.x = fmaf(at1[v], wv.x, a1.x);
                a0.y = fmaf(at0[v], wv.y, a0.y); a1.y = fmaf(at1[v], wv.y, a1.y);
                a0.z = fmaf(at0[v], wv.z, a0.z); a1.z = fmaf(at1[v], wv.z, a1.z);
                a0.w = fmaf(at0[v], wv.w, a0.w); a1.w = fmaf(at1[v], wv.w, a1.w);
            }
            float* D = &sm[(which ? OFF_A1 : OFF_A0)];
            D[(w4 + 0) * 36 + u] = a0.x;  D[1152 + (w4 + 0) * 36 + u] = a1.x;
            D[(w4 + 1) * 36 + u] = a0.y;  D[1152 + (w4 + 1) * 36 + u] = a1.y;
            D[(w4 + 2) * 36 + u] = a0.z;  D[1152 + (w4 + 2) * 36 + u] = a1.z;
            D[(w4 + 3) * 36 + u] = a0.w;  D[1152 + (w4 + 3) * 36 + u] = a1.w;
        }
        __syncthreads();

        // --- consume: 2 nodes x 128 outputs ---
        int t = tid >> 7;
        int j = tid & 127;
        int n = n0 + t;
        if (j < 32) {
            // scalar channel j
            const float4* Arow = (const float4*)&sm[OFF_A0 + t * 1152 + j * 36];
            const float4* Srow = (const float4*)&sm[OFF_S + t * 32];
            float sc = 0.f;
#pragma unroll
            for (int u4 = 0; u4 < 8; u4++) {
                float4 a = Arow[u4], s4 = Srow[u4];
                sc = fmaf(a.x, s4.x, sc); sc = fmaf(a.y, s4.y, sc);
                sc = fmaf(a.z, s4.z, sc); sc = fmaf(a.w, s4.w, sc);
            }
            const float4* Wrow = (const float4*)&sm[OFF_W20 + j * 68];
            const float4* Ag   = (const float4*)&sm[OFF_AGS + t * 64];
            float acc = 0.f;
#pragma unroll
            for (int k4 = 0; k4 < 16; k4++) {
                float4 wv = Wrow[k4], av = Ag[k4];
                acc = fmaf(wv.x, av.x, acc); acc = fmaf(wv.y, av.y, acc);
                acc = fmaf(wv.z, av.z, acc); acc = fmaf(wv.w, av.w, acc);
            }
            out[n * 128 + j] = acc * c_agg + sc * c_sc;
        } else {
            int idx = j - 32;
            int d = idx >> 5, w = idx & 31;
            const float4* Arow = (const float4*)&sm[OFF_A1 + t * 1152 + w * 36];
            const float4* Vrow = (const float4*)&sm[OFF_VD + t * 96 + d * 32];
            float sc = 0.f;
#pragma unroll
            for (int u4 = 0; u4 < 8; u4++) {
                float4 a = Arow[u4], v4 = Vrow[u4];
                sc = fmaf(a.x, v4.x, sc); sc = fmaf(a.y, v4.y, sc);
                sc = fmaf(a.z, v4.z, sc); sc = fmaf(a.w, v4.w, sc);
            }
            const float4* Wrow = (const float4*)&sm[OFF_W21 + w * 68];
            const float4* Ag   = (const float4*)&sm[OFF_AGV + t * 192 + d * 64];
            float acc = 0.f;
#pragma unroll
            for (int k4 = 0; k4 < 16; k4++) {
                float4 wv = Wrow[k4], av = Ag[k4];
                acc = fmaf(wv.x, av.x, acc); acc = fmaf(wv.y, av.y, acc);
                acc = fmaf(wv.z, av.z, acc); acc = fmaf(wv.w, av.w, acc);
            }
            out[n * 128 + 32 + w * 3 + d] = acc * c_agg + sc * c_sc;
        }
    }
}

// ---------------------------------------------------------------------------
extern "C" void kernel_launch(void* const* d_in, const int* in_sizes, int n_in,
                              void* d_out, int out_size) {
    const float* node_s       = (const float*)d_in[0];
    const float* node_v       = (const float*)d_in[1];
    const float* node_attr    = (const float*)d_in[2];
    const float* edge_attr    = (const float*)d_in[3];
    const float* edge_scalars = (const float*)d_in[4];
    const float* W1_0         = (const float*)d_in[5];
    const float* W1_1         = (const float*)d_in[6];
    const float* Wfc1         = (const float*)d_in[7];
    const float* Wfc2         = (const float*)d_in[8];
    const float* W2_0         = (const float*)d_in[9];
    const float* W2_1         = (const float*)d_in[10];
    const float* Wsc0         = (const float*)d_in[11];
    const float* Wsc1         = (const float*)d_in[12];
    const int*   edge_src     = (const int*)d_in[13];
    const int*   edge_dst     = (const int*)d_in[14];
    float* out = (float*)d_out;

    cudaFuncSetAttribute(node_post2_kernel,
                         cudaFuncAttributeMaxDynamicSharedMemorySize, SM_BYTES);

    node_pre_kernel<<<(NN * 32 + 255) / 256, 256>>>(node_s, node_v, W1_0, W1_1);
    hist_kernel<<<(EE + 255) / 256, 256>>>(edge_src);
    scan_kernel<<<1, 1024>>>();
    scatter_kernel<<<(EE + 255) / 256, 256>>>(edge_src);
    edge_agg_kernel<<<(NN + 7) / 8, 256>>>(edge_attr, edge_scalars, Wfc1, Wfc2,
                                           edge_dst);
    node_post2_kernel<<<NN / 16, 256, SM_BYTES>>>(node_s, node_v, node_attr,
                                                  W2_0, W2_1, Wsc0, Wsc1, out);
}